// round 10
// baseline (speedup 1.0000x reference)
#include <cuda_runtime.h>
#include <cuda_fp16.h>
#include <cstdint>

#define NB 4
#define NC 256
#define NN 4096
#define TI 128
#define TJ 64
#define NSTEPS (NN / TJ)
#define TJ1 256
#define NSTEPS1 (NN / TJ1)

// ---------------- device scratch (allocation-free) ----------------
__device__ unsigned short g_q[(size_t)NB * NN * 64];     // [b][n][32hi|32lo] fp16
__device__ unsigned short g_k[(size_t)NB * NN * 64];
__device__ unsigned short g_v[(size_t)NB * NC * NN];     // [b][c][n] fp16

// ---------------- attn SMEM layout (bytes) ----------------
#define SQ 0                       // 128 rows x 128B = 16384
#define SK 16384                   // + bf*8192 (64 rows x 128B)
#define SV 32768                   // + bf*32768 ; 256 c-rows x 128B (64 j fp16)
#define SMEMB (32768 + 2 * 32768)  // 98304

// ---------------- proj SMEM layout ----------------
#define PJ_SX 0        // x B-tile: [2 buf][32 k][512B: 128n hi | 128n lo] = 32768
#define PJ_SW 32768    // W A-tile: [2 buf][128 c][128B: 32k hi | 32k lo] = 32768
#define PJ_SMEM 65536

// ---------------- PTX helpers ----------------
__device__ __forceinline__ uint32_t smem_u32(const void* p) {
    uint32_t a;
    asm("{ .reg .u64 t; cvta.to.shared.u64 t, %1; cvt.u32.u64 %0, t; }" : "=r"(a) : "l"(p));
    return a;
}
__device__ __forceinline__ void cp16(uint32_t dst, const void* src) {
    asm volatile("cp.async.cg.shared.global [%0], [%1], 16;" :: "r"(dst), "l"(src));
}
__device__ __forceinline__ void cp_commit() { asm volatile("cp.async.commit_group;" ::: "memory"); }
__device__ __forceinline__ void cp_wait0()  { asm volatile("cp.async.wait_group 0;" ::: "memory"); }

__device__ __forceinline__ void ldsm4(uint32_t* r, uint32_t a) {
    asm volatile("ldmatrix.sync.aligned.m8n8.x4.shared.b16 {%0,%1,%2,%3}, [%4];"
        : "=r"(r[0]), "=r"(r[1]), "=r"(r[2]), "=r"(r[3]) : "r"(a));
}
__device__ __forceinline__ void ldsm4t(uint32_t* r, uint32_t a) {
    asm volatile("ldmatrix.sync.aligned.m8n8.x4.trans.shared.b16 {%0,%1,%2,%3}, [%4];"
        : "=r"(r[0]), "=r"(r[1]), "=r"(r[2]), "=r"(r[3]) : "r"(a));
}
__device__ __forceinline__ void mma16816(float* d, const uint32_t* a, uint32_t b0, uint32_t b1) {
    asm volatile("mma.sync.aligned.m16n8k16.row.col.f32.f16.f16.f32 "
        "{%0,%1,%2,%3}, {%4,%5,%6,%7}, {%8,%9}, {%0,%1,%2,%3};"
        : "+f"(d[0]), "+f"(d[1]), "+f"(d[2]), "+f"(d[3])
        : "r"(a[0]), "r"(a[1]), "r"(a[2]), "r"(a[3]), "r"(b0), "r"(b1));
}
__device__ __forceinline__ void sts128(uint32_t a, uint32_t r0, uint32_t r1, uint32_t r2, uint32_t r3) {
    asm volatile("st.shared.v4.b32 [%0], {%1,%2,%3,%4};"
        :: "r"(a), "r"(r0), "r"(r1), "r"(r2), "r"(r3) : "memory");
}
// pack: first arg -> low half, second -> high half
__device__ __forceinline__ uint32_t packh(float lo, float hi) {
    uint32_t r;
    asm("cvt.rn.f16x2.f32 %0, %1, %2;" : "=r"(r) : "f"(hi), "f"(lo));
    return r;
}
__device__ __forceinline__ unsigned short f16h(float v) {
    __half h = __float2half_rn(v);
    return *reinterpret_cast<unsigned short*>(&h);
}
__device__ __forceinline__ float f16f(unsigned short u) {
    __half h = *reinterpret_cast<__half*>(&u);
    return __half2float(h);
}

// ---------------- attn prefetchers (256 threads) ----------------
// phase 1: K hi-plane, 256 rows x 64B, swizzled for 64B-row ldsm
__device__ __forceinline__ void prefetch_k256(uint32_t sb, int bf, int b, int j0, int t) {
    #pragma unroll
    for (int kk = 0; kk < 4; kk++) {
        int idx = t + kk * 256;
        int row = idx >> 2, ch = idx & 3;
        cp16(sb + SV + bf * 16384 + row * 64 + ((ch ^ ((row >> 1) & 3)) << 4),
             g_k + ((size_t)(b * NN + j0 + row)) * 64 + ch * 8);
    }
}
// phase 2: full K (hi+lo) + V ([256 c][64 j] rows of 128B)
__device__ __forceinline__ void prefetch_kv(uint32_t sb, int bf, int b, int j0, int t) {
    const unsigned short* ks = g_k + ((size_t)(b * NN + j0)) * 64;
    #pragma unroll
    for (int kk = 0; kk < 2; kk++) {
        int idx = t + kk * 256;
        int row = idx >> 3, ch = idx & 7;
        cp16(sb + SK + bf * 8192 + row * 128 + ((ch ^ (row & 7)) << 4),
             ks + (size_t)row * 64 + ch * 8);
    }
    const unsigned short* vs = g_v + ((size_t)b * NC) * NN + j0;
    #pragma unroll
    for (int kk = 0; kk < 8; kk++) {
        int idx = t + kk * 256;
        int c = idx >> 3, ch = idx & 7;
        cp16(sb + SV + bf * 32768 + c * 128 + ((ch ^ (c & 7)) << 4),
             vs + (size_t)c * NN + ch * 8);
    }
}

// =====================================================================
// fp16 mma.sync flash attention (TI=128, 8 warps, exact max pre-pass)
// V tile now [c][j] -> non-trans ldsm for PV.
// =====================================================================
__global__ __launch_bounds__(256, 1) void attn_kernel(
    const float* __restrict__ x, float* __restrict__ out)
{
    extern __shared__ char smem[];
    const uint32_t sb = smem_u32(smem);
    const int t = threadIdx.x, lane = t & 31, w = t >> 5;
    const int b = blockIdx.y, i0 = blockIdx.x * TI;
    const int rr = lane >> 2, qd = lane & 3;
    const int l7 = lane & 7, lm8 = ((lane >> 3) & 1) * 8, lhi = lane >> 4, lm4 = lane >> 3;

    // ---- prefetch Q tile + first phase-1 K tile ----
    {
        const unsigned short* qs = g_q + ((size_t)(b * NN + i0)) * 64;
        #pragma unroll
        for (int kk = 0; kk < 4; kk++) {
            int idx = t + kk * 256;
            int row = idx >> 3, ch = idx & 7;
            cp16(sb + SQ + row * 128 + ((ch ^ (row & 7)) << 4),
                 qs + (size_t)row * 64 + ch * 8);
        }
        prefetch_k256(sb, 0, b, 0, t);
        cp_commit();
    }
    cp_wait0();
    __syncthreads();

    // ---- resident Q fragments (hi/lo, 2 k-chunks) ----
    uint32_t qh[2][4], ql[2][4];
    #pragma unroll
    for (int kc = 0; kc < 2; kc++) {
        int row = w * 16 + l7 + lm8;
        int chh = 2 * kc + lhi;
        ldsm4(qh[kc], sb + SQ + row * 128 + ((chh ^ (row & 7)) << 4));
        ldsm4(ql[kc], sb + SQ + row * 128 + (((chh + 4) ^ (row & 7)) << 4));
    }

    // ================= PHASE 1: row max (16 big tiles) =================
    float mx0 = -1e30f, mx1 = -1e30f;
    for (int it = 0; it < NSTEPS1; it++) {
        const int bf = it & 1;
        if (it > 0) { cp_wait0(); __syncthreads(); }
        if (it + 1 < NSTEPS1) { prefetch_k256(sb, bf ^ 1, b, (it + 1) * TJ1, t); cp_commit(); }
        const uint32_t kb = sb + SV + bf * 16384;
        #pragma unroll
        for (int hb = 0; hb < 32; hb++) {
            float S[4] = {0.f, 0.f, 0.f, 0.f};
            int krow = hb * 8 + l7;
            uint32_t a = kb + krow * 64 + ((lm4 ^ ((krow >> 1) & 3)) << 4);
            uint32_t kh4[4];
            ldsm4(kh4, a);
            mma16816(S, qh[0], kh4[0], kh4[1]);
            mma16816(S, qh[1], kh4[2], kh4[3]);
            mx0 = fmaxf(mx0, fmaxf(S[0], S[1]));
            mx1 = fmaxf(mx1, fmaxf(S[2], S[3]));
        }
    }
    mx0 = fmaxf(mx0, __shfl_xor_sync(0xffffffffu, mx0, 1));
    mx0 = fmaxf(mx0, __shfl_xor_sync(0xffffffffu, mx0, 2));
    mx1 = fmaxf(mx1, __shfl_xor_sync(0xffffffffu, mx1, 1));
    mx1 = fmaxf(mx1, __shfl_xor_sync(0xffffffffu, mx1, 2));

    // ================= PHASE 2: attention =================
    float O[32][4];
    #pragma unroll
    for (int i = 0; i < 32; i++)
        #pragma unroll
        for (int j = 0; j < 4; j++) O[i][j] = 0.f;
    float rs0 = 0.f, rs1 = 0.f;

    __syncthreads();          // all phase-1 reads of SV region done
    prefetch_kv(sb, 0, b, 0, t);
    cp_commit();
    cp_wait0();
    __syncthreads();

    for (int st = 0; st < NSTEPS; st++) {
        const int bf = st & 1;
        if (st > 0) { cp_wait0(); __syncthreads(); }
        if (st + 1 < NSTEPS) { prefetch_kv(sb, bf ^ 1, b, (st + 1) * TJ, t); cp_commit(); }

        const uint32_t kbase = sb + SK + bf * 8192;
        const uint32_t vbase = sb + SV + bf * 32768;

        #pragma unroll
        for (int kcp = 0; kcp < 2; kcp++) {
            uint32_t pa[2][4];
            #pragma unroll
            for (int kc2 = 0; kc2 < 2; kc2++) {
                const int kc = kcp * 2 + kc2;
                // ---- S for j-blocks 2kc, 2kc+1 (3-product hi/lo) ----
                float S[2][4];
                #pragma unroll
                for (int h = 0; h < 2; h++) {
                    S[h][0] = S[h][1] = S[h][2] = S[h][3] = 0.f;
                    int krow = (2 * kc + h) * 8 + l7;
                    int swk = (krow & 7);
                    uint32_t kh4[4], kl4[4];
                    ldsm4(kh4, kbase + krow * 128 + ((lm4 ^ swk) << 4));
                    ldsm4(kl4, kbase + krow * 128 + (((lm4 + 4) ^ swk) << 4));
                    mma16816(S[h], qh[0], kh4[0], kh4[1]);
                    mma16816(S[h], qh[1], kh4[2], kh4[3]);
                    mma16816(S[h], qh[0], kl4[0], kl4[1]);
                    mma16816(S[h], qh[1], kl4[2], kl4[3]);
                    mma16816(S[h], ql[0], kh4[0], kh4[1]);
                    mma16816(S[h], ql[1], kh4[2], kh4[3]);
                }
                // ---- p = exp(s - m), fp16 pack ----
                #pragma unroll
                for (int h = 0; h < 2; h++) {
                    float e0 = __expf(S[h][0] - mx0), e1 = __expf(S[h][1] - mx0);
                    float e2 = __expf(S[h][2] - mx1), e3 = __expf(S[h][3] - mx1);
                    rs0 += e0 + e1;
                    rs1 += e2 + e3;
                    pa[kc2][h * 2]     = packh(e0, e1);
                    pa[kc2][h * 2 + 1] = packh(e2, e3);
                }
            }
            // ---- O += P @ V (V tile [c][j], non-trans ldsm, 32 c-blocks) ----
            #pragma unroll
            for (int cb = 0; cb < 32; cb++) {
                int crow = cb * 8 + l7;
                int ch = 4 * kcp + lm4;
                uint32_t v4[4];
                ldsm4(v4, vbase + crow * 128 + ((ch ^ (crow & 7)) << 4));
                mma16816(O[cb], pa[0], v4[0], v4[1]);
                mma16816(O[cb], pa[1], v4[2], v4[3]);
            }
        }
    }

    // ---- row-sum reduce + epilogue (O/l + residual) ----
    rs0 += __shfl_xor_sync(0xffffffffu, rs0, 1);
    rs0 += __shfl_xor_sync(0xffffffffu, rs0, 2);
    rs1 += __shfl_xor_sync(0xffffffffu, rs1, 1);
    rs1 += __shfl_xor_sync(0xffffffffu, rs1, 2);
    const float li0 = 1.0f / rs0, li1 = 1.0f / rs1;

    const int ng = i0 + w * 16 + rr;
    #pragma unroll
    for (int nb = 0; nb < 32; nb++) {
        int c = nb * 8 + qd * 2;
        size_t g = ((size_t)b * NC + c) * NN + ng;
        out[g]          = O[nb][0] * li0 + x[g];
        out[g + NN]     = O[nb][1] * li0 + x[g + NN];
        out[g + 8]      = O[nb][2] * li1 + x[g + 8];
        out[g + 8 + NN] = O[nb][3] * li1 + x[g + 8 + NN];
    }
}

// =====================================================================
// Tensor-core projections: one kernel.
// blocks 0-63:  V path  (n0 = (bx>>1)*128, c-tile = (bx&1)*128)
// blocks 64-95: QK path (n0 = (bx-64)*128, Wq|Wk stacked 64 c-rows)
// A = W [c][k] (Q-tile format), B = x [k][n] (V-tile format), 3-product fp16.
// =====================================================================
__global__ __launch_bounds__(256, 1) void proj_mma(
    const float* __restrict__ x,
    const float* __restrict__ Wq, const float* __restrict__ bq,
    const float* __restrict__ Wk, const float* __restrict__ bk,
    const float* __restrict__ Wv, const float* __restrict__ bv,
    unsigned short* __restrict__ oq, unsigned short* __restrict__ ok,
    unsigned short* __restrict__ vh)
{
    extern __shared__ char ps[];
    const uint32_t sb = smem_u32(ps);
    const int t = threadIdx.x, lane = t & 31, w = t >> 5;
    const int b = blockIdx.z;
    const bool isV = blockIdx.x < 64;
    const int n0 = isV ? ((blockIdx.x >> 1) * 128) : ((int)(blockIdx.x - 64) * 128);
    const int c0 = isV ? ((blockIdx.x & 1) * 128) : 0;
    const int rr = lane >> 2, qd = lane & 3;
    const int l7 = lane & 7, lm8 = ((lane >> 3) & 1) * 8, lhi = lane >> 4;

    // load positions
    const int xkr = t >> 3, xnn = (t & 7) * 16;
    const int wc = t >> 1, wks = (t & 1) * 16;
    const float* xsrc = x + ((size_t)b * NC) * NN + n0 + xnn;   // + (k0+xkr)*NN
    const float* wsrc = nullptr;
    bool wact;
    if (isV) { wact = true; wsrc = Wv + (size_t)(c0 + wc) * NC + wks; }
    else {
        wact = (t < 128);
        if (wact) wsrc = (wc < 32 ? Wq + (size_t)wc * NC
                                  : Wk + (size_t)(wc - 32) * NC) + wks;
    }

    float4 xa[4], wa[4];
    {
        const float* sx = xsrc + (size_t)xkr * NN;
        xa[0] = ((const float4*)sx)[0]; xa[1] = ((const float4*)sx)[1];
        xa[2] = ((const float4*)sx)[2]; xa[3] = ((const float4*)sx)[3];
        if (wact) {
            wa[0] = ((const float4*)wsrc)[0]; wa[1] = ((const float4*)wsrc)[1];
            wa[2] = ((const float4*)wsrc)[2]; wa[3] = ((const float4*)wsrc)[3];
        }
    }

    float O[16][4];
    #pragma unroll
    for (int i = 0; i < 16; i++)
        #pragma unroll
        for (int j = 0; j < 4; j++) O[i][j] = 0.f;

    for (int it = 0; it < 8; it++) {
        const int buf = it & 1;
        // ---- convert + STS current tiles ----
        {
            uint32_t xb2 = sb + PJ_SX + buf * 16384 + xkr * 512;
            int swx = xkr & 7;
            #pragma unroll
            for (int cc = 0; cc < 2; cc++) {
                const float* f = (const float*)&xa[cc * 2];
                uint32_t hi[4], lo[4];
                #pragma unroll
                for (int p = 0; p < 4; p++) {
                    float v0 = f[2 * p], v1 = f[2 * p + 1];
                    uint32_t hp = packh(v0, v1);
                    float r0 = f16f((unsigned short)(hp & 0xffffu));
                    float r1 = f16f((unsigned short)(hp >> 16));
                    hi[p] = hp;
                    lo[p] = packh(v0 - r0, v1 - r1);
                }
                int ch = (xnn >> 3) + cc, chl = ch + 16;
                sts128(xb2 + (((ch & 24) | ((ch ^ swx) & 7)) << 4), hi[0], hi[1], hi[2], hi[3]);
                sts128(xb2 + (((chl & 24) | ((chl ^ swx) & 7)) << 4), lo[0], lo[1], lo[2], lo[3]);
            }
            if (wact) {
                uint32_t wb2 = sb + PJ_SW + buf * 16384 + wc * 128;
                int sww = wc & 7;
                #pragma unroll
                for (int cc = 0; cc < 2; cc++) {
                    const float* f = (const float*)&wa[cc * 2];
                    uint32_t hi[4], lo[4];
                    #pragma unroll
                    for (int p = 0; p < 4; p++) {
                        float v0 = f[2 * p], v1 = f[2 * p + 1];
                        uint32_t hp = packh(v0, v1);
                        float r0 = f16f((unsigned short)(hp & 0xffffu));
                        float r1 = f16f((unsigned short)(hp >> 16));
                        hi[p] = hp;
                        lo[p] = packh(v0 - r0, v1 - r1);
                    }
                    int ch = (wks >> 3) + cc, chl = ch + 4;
                    sts128(wb2 + (((ch ^ sww) & 7) << 4), hi[0], hi[1], hi[2], hi[3]);
                    sts128(wb2 + (((chl ^ sww) & 7) << 4), lo[0], lo[1], lo[2], lo[3]);
                }
            }
        }
        __syncthreads();

        // ---- prefetch next k-tile into registers ----
        if (it < 7) {
            int k0n = (it + 1) * 32;
            const float* sx = xsrc + (size_t)(k0n + xkr) * NN;
            xa[0] = ((const float4*)sx)[0]; xa[1] = ((const float4*)sx)[1];
            xa[2] = ((const float4*)sx)[2]; xa[3] = ((const float4*)sx)[3];
            if (wact) {
                const float* sw = wsrc + k0n;
                wa[0] = ((const float4*)sw)[0]; wa[1] = ((const float4*)sw)[1];
                wa[2] = ((const float4*)sw)[2]; wa[3] = ((const float4*)sw)[3];
            }
        }

        // ---- mainloop ----
        const uint32_t abase = sb + PJ_SW + buf * 16384;
        const uint32_t bbase = sb + PJ_SX + buf * 16384;
        const int arow = (isV ? w * 16 : (w & 3) * 16) + l7 + lm8;
        const int swa = arow & 7;
        const int nub = isV ? 8 : 4;
        const int cho = isV ? 0 : ((w >> 2) * 8);
        #pragma unroll
        for (int kc = 0; kc < 2; kc++) {
            uint32_t ah[4], al[4];
            int chh = 2 * kc + lhi;
            ldsm4(ah, abase + arow * 128 + ((chh ^ swa) << 4));
            ldsm4(al, abase + arow * 128 + (((chh + 4) ^ swa) << 4));
            int vrow = kc * 16 + l7 + lm8;
            uint32_t vb2 = bbase + vrow * 512;
            int swv = vrow & 7;
            for (int u = 0; u < nub; u++) {
                int ch = cho + 2 * u + lhi, chl = ch + 16;
                uint32_t bh[4], bl[4];
                ldsm4t(bh, vb2 + (((ch & 24) | ((ch ^ swv) & 7)) << 4));
                ldsm4t(bl, vb2 + (((chl & 24) | ((chl ^ swv) & 7)) << 4));
                mma16816(O[2 * u],     ah, bh[0], bh[1]);
                mma16816(O[2 * u + 1], ah, bh[2], bh[3]);
                mma16816(O[2 * u],     al, bh[0], bh[1]);
                mma16816(O[2 * u + 1], al, bh[2], bh[3]);
                mma16816(O[2 * u],     ah, bl[0], bl[1]);
                mma16816(O[2 * u + 1], ah, bl[2], bl[3]);
            }
        }
    }

    // ---- epilogues ----
    if (isV) {
        const int c = c0 + w * 16 + rr;
        const float b0 = bv[c], b1 = bv[c + 8];
        unsigned short* v0p = vh + ((size_t)b * NC + c) * NN;
        unsigned short* v1p = vh + ((size_t)b * NC + c + 8) * NN;
        #pragma unroll
        for (int u = 0; u < 16; u++) {
            int n = n0 + u * 8 + qd * 2;
            *(uint32_t*)&v0p[n] = packh(O[u][0] + b0, O[u][1] + b0);
            *(uint32_t*)&v1p[n] = packh(O[u][2] + b1, O[u][3] + b1);
        }
    } else {
        const int cbase = (w & 3) * 16 + rr;
        const int nbase = n0 + (w >> 2) * 64;
        #pragma unroll
        for (int ri = 0; ri < 2; ri++) {
            int cc = cbase + ri * 8;
            bool isq = (cc < 32);
            unsigned short* tgt = isq ? oq : ok;
            int ccl = isq ? cc : cc - 32;
            float bias = isq ? bq[cc] : bk[cc - 32];
            #pragma unroll
            for (int u = 0; u < 8; u++) {
                int n = nbase + u * 8 + qd * 2;
                float v0 = O[u][2 * ri] + bias;
                float v1 = O[u][2 * ri + 1] + bias;
                unsigned short h0 = f16h(v0);
                unsigned short h1 = f16h(v1);
                size_t b0i = ((size_t)(b * NN + n)) * 64;
                size_t b1i = b0i + 64;
                tgt[b0i + ccl]      = h0;
                tgt[b0i + 32 + ccl] = f16h(v0 - f16f(h0));
                tgt[b1i + ccl]      = h1;
                tgt[b1i + 32 + ccl] = f16h(v1 - f16f(h1));
            }
        }
    }
}

// =====================================================================
extern "C" void kernel_launch(void* const* d_in, const int* in_sizes, int n_in,
                              void* d_out, int out_size)
{
    const float* x  = (const float*)d_in[0];
    const float* Wq = (const float*)d_in[1];
    const float* bq = (const float*)d_in[2];
    const float* Wk = (const float*)d_in[3];
    const float* bk = (const float*)d_in[4];
    const float* Wv = (const float*)d_in[5];
    const float* bv = (const float*)d_in[6];
    float* out = (float*)d_out;

    unsigned short *pq, *pk, *pv;
    cudaGetSymbolAddress((void**)&pq, g_q);
    cudaGetSymbolAddress((void**)&pk, g_k);
    cudaGetSymbolAddress((void**)&pv, g_v);

    cudaFuncSetAttribute(attn_kernel, cudaFuncAttributeMaxDynamicSharedMemorySize, SMEMB);
    cudaFuncSetAttribute(proj_mma, cudaFuncAttributeMaxDynamicSharedMemorySize, PJ_SMEM);

    proj_mma<<<dim3(96, 1, NB), 256, PJ_SMEM>>>(x, Wq, bq, Wk, bk, Wv, bv, pq, pk, pv);
    attn_kernel<<<dim3(NN / TI, NB), 256, SMEMB>>>(x, out);
}

// round 12
// speedup vs baseline: 1.3452x; 1.3452x over previous
#include <cuda_runtime.h>
#include <cuda_fp16.h>
#include <cstdint>

#define NB 4
#define NC 256
#define NN 4096
#define TI 128
#define TJ 64
#define NSTEPS (NN / TJ)
#define TJ1 256
#define NSTEPS1 (NN / TJ1)

// ---------------- device scratch (allocation-free) ----------------
__device__ unsigned short g_q[(size_t)NB * NN * 64];     // [b][n][32hi|32lo] fp16
__device__ unsigned short g_k[(size_t)NB * NN * 64];
__device__ unsigned short g_v[(size_t)NB * NN * 256];    // [b][n][c] fp16
__device__ unsigned short g_xh[(size_t)NB * NC * NN];    // x hi plane [b][c][n]
__device__ unsigned short g_xl[(size_t)NB * NC * NN];    // x lo plane
__device__ unsigned short g_wvh[256 * 256];              // Wv hi [c][k]
__device__ unsigned short g_wvl[256 * 256];
__device__ unsigned short g_wqkh[64 * 256];              // Wq(0-31)|Wk(32-63) hi [c][k]
__device__ unsigned short g_wqkl[64 * 256];

// ---------------- attn SMEM layout (bytes) ----------------
#define SQ 0                       // 128 rows x 128B = 16384
#define SK 16384                   // + bf*8192 (64 rows x 128B)
#define SV 32768                   // + bf*32768 ; 64 j-rows x 512B
#define SMEMB (32768 + 2 * 32768)  // 98304

// ---------------- proj SMEM ----------------
#define PJX 0          // x tile: [2 buf][32 k][512B: 128n hi | 128n lo]
#define PJW 32768      // W tile: [2 buf][<=128 c][128B: 32k hi | 32k lo]
#define PJ_SMEM 65536

// ---------------- PTX helpers ----------------
__device__ __forceinline__ uint32_t smem_u32(const void* p) {
    uint32_t a;
    asm("{ .reg .u64 t; cvta.to.shared.u64 t, %1; cvt.u32.u64 %0, t; }" : "=r"(a) : "l"(p));
    return a;
}
__device__ __forceinline__ void cp16(uint32_t dst, const void* src) {
    asm volatile("cp.async.cg.shared.global [%0], [%1], 16;" :: "r"(dst), "l"(src));
}
__device__ __forceinline__ void cp_commit() { asm volatile("cp.async.commit_group;" ::: "memory"); }
__device__ __forceinline__ void cp_wait0()  { asm volatile("cp.async.wait_group 0;" ::: "memory"); }

__device__ __forceinline__ void ldsm4(uint32_t* r, uint32_t a) {
    asm volatile("ldmatrix.sync.aligned.m8n8.x4.shared.b16 {%0,%1,%2,%3}, [%4];"
        : "=r"(r[0]), "=r"(r[1]), "=r"(r[2]), "=r"(r[3]) : "r"(a));
}
__device__ __forceinline__ void ldsm4t(uint32_t* r, uint32_t a) {
    asm volatile("ldmatrix.sync.aligned.m8n8.x4.trans.shared.b16 {%0,%1,%2,%3}, [%4];"
        : "=r"(r[0]), "=r"(r[1]), "=r"(r[2]), "=r"(r[3]) : "r"(a));
}
__device__ __forceinline__ void mma16816(float* d, const uint32_t* a, uint32_t b0, uint32_t b1) {
    asm volatile("mma.sync.aligned.m16n8k16.row.col.f32.f16.f16.f32 "
        "{%0,%1,%2,%3}, {%4,%5,%6,%7}, {%8,%9}, {%0,%1,%2,%3};"
        : "+f"(d[0]), "+f"(d[1]), "+f"(d[2]), "+f"(d[3])
        : "r"(a[0]), "r"(a[1]), "r"(a[2]), "r"(a[3]), "r"(b0), "r"(b1));
}
// pack: first arg -> low half, second -> high half
__device__ __forceinline__ uint32_t packh(float lo, float hi) {
    uint32_t r;
    asm("cvt.rn.f16x2.f32 %0, %1, %2;" : "=r"(r) : "f"(hi), "f"(lo));
    return r;
}
__device__ __forceinline__ unsigned short f16h(float v) {
    __half h = __float2half_rn(v);
    return *reinterpret_cast<unsigned short*>(&h);
}
__device__ __forceinline__ float f16f(unsigned short u) {
    __half h = *reinterpret_cast<__half*>(&u);
    return __half2float(h);
}
__device__ __forceinline__ uint32_t swz512(int ch, int row) {
    return (uint32_t)(((ch & 24) | ((ch ^ (row & 7)) & 7)) << 4);
}

// ---------------- attn prefetchers (256 threads) ----------------
__device__ __forceinline__ void prefetch_k256(uint32_t sb, int bf, int b, int j0, int t) {
    #pragma unroll
    for (int kk = 0; kk < 4; kk++) {
        int idx = t + kk * 256;
        int row = idx >> 2, ch = idx & 3;
        cp16(sb + SV + bf * 16384 + row * 64 + ((ch ^ ((row >> 1) & 3)) << 4),
             g_k + ((size_t)(b * NN + j0 + row)) * 64 + ch * 8);
    }
}
__device__ __forceinline__ void prefetch_kv(uint32_t sb, int bf, int b, int j0, int t) {
    const unsigned short* ks = g_k + ((size_t)(b * NN + j0)) * 64;
    #pragma unroll
    for (int kk = 0; kk < 2; kk++) {
        int idx = t + kk * 256;
        int row = idx >> 3, ch = idx & 7;
        cp16(sb + SK + bf * 8192 + row * 128 + ((ch ^ (row & 7)) << 4),
             ks + (size_t)row * 64 + ch * 8);
    }
    const unsigned short* hs = g_v + ((size_t)(b * NN + j0)) * 256;
    #pragma unroll
    for (int kk = 0; kk < 8; kk++) {
        int idx = t + kk * 256;
        int row = idx >> 5, ch = idx & 31;
        uint32_t off = row * 512 + (((ch & 24) | ((ch ^ row) & 7)) << 4);
        cp16(sb + SV + bf * 32768 + off, hs + (size_t)row * 256 + ch * 8);
    }
}

// =====================================================================
// fp16 mma.sync flash attention (round-9 validated: TI=128, 8 warps)
// =====================================================================
__global__ __launch_bounds__(256, 1) void attn_kernel(
    const float* __restrict__ x, float* __restrict__ out)
{
    extern __shared__ char smem[];
    const uint32_t sb = smem_u32(smem);
    const int t = threadIdx.x, lane = t & 31, w = t >> 5;
    const int b = blockIdx.y, i0 = blockIdx.x * TI;
    const int rr = lane >> 2, qd = lane & 3;
    const int l7 = lane & 7, lm8 = ((lane >> 3) & 1) * 8, lhi = lane >> 4, lm4 = lane >> 3;

    {
        const unsigned short* qs = g_q + ((size_t)(b * NN + i0)) * 64;
        #pragma unroll
        for (int kk = 0; kk < 4; kk++) {
            int idx = t + kk * 256;
            int row = idx >> 3, ch = idx & 7;
            cp16(sb + SQ + row * 128 + ((ch ^ (row & 7)) << 4),
                 qs + (size_t)row * 64 + ch * 8);
        }
        prefetch_k256(sb, 0, b, 0, t);
        cp_commit();
    }
    cp_wait0();
    __syncthreads();

    uint32_t qh[2][4], ql[2][4];
    #pragma unroll
    for (int kc = 0; kc < 2; kc++) {
        int row = w * 16 + l7 + lm8;
        int chh = 2 * kc + lhi;
        ldsm4(qh[kc], sb + SQ + row * 128 + ((chh ^ (row & 7)) << 4));
        ldsm4(ql[kc], sb + SQ + row * 128 + (((chh + 4) ^ (row & 7)) << 4));
    }

    // ---- PHASE 1: row max ----
    float mx0 = -1e30f, mx1 = -1e30f;
    for (int it = 0; it < NSTEPS1; it++) {
        const int bf = it & 1;
        if (it > 0) { cp_wait0(); __syncthreads(); }
        if (it + 1 < NSTEPS1) { prefetch_k256(sb, bf ^ 1, b, (it + 1) * TJ1, t); cp_commit(); }
        const uint32_t kb = sb + SV + bf * 16384;
        #pragma unroll
        for (int hb = 0; hb < 32; hb++) {
            float S[4] = {0.f, 0.f, 0.f, 0.f};
            int krow = hb * 8 + l7;
            uint32_t a = kb + krow * 64 + ((lm4 ^ ((krow >> 1) & 3)) << 4);
            uint32_t kh4[4];
            ldsm4(kh4, a);
            mma16816(S, qh[0], kh4[0], kh4[1]);
            mma16816(S, qh[1], kh4[2], kh4[3]);
            mx0 = fmaxf(mx0, fmaxf(S[0], S[1]));
            mx1 = fmaxf(mx1, fmaxf(S[2], S[3]));
        }
    }
    mx0 = fmaxf(mx0, __shfl_xor_sync(0xffffffffu, mx0, 1));
    mx0 = fmaxf(mx0, __shfl_xor_sync(0xffffffffu, mx0, 2));
    mx1 = fmaxf(mx1, __shfl_xor_sync(0xffffffffu, mx1, 1));
    mx1 = fmaxf(mx1, __shfl_xor_sync(0xffffffffu, mx1, 2));

    // ---- PHASE 2 ----
    float O[32][4];
    #pragma unroll
    for (int i = 0; i < 32; i++)
        #pragma unroll
        for (int j = 0; j < 4; j++) O[i][j] = 0.f;
    float rs0 = 0.f, rs1 = 0.f;

    __syncthreads();
    prefetch_kv(sb, 0, b, 0, t);
    cp_commit();
    cp_wait0();
    __syncthreads();

    for (int st = 0; st < NSTEPS; st++) {
        const int bf = st & 1;
        if (st > 0) { cp_wait0(); __syncthreads(); }
        if (st + 1 < NSTEPS) { prefetch_kv(sb, bf ^ 1, b, (st + 1) * TJ, t); cp_commit(); }

        const uint32_t kbase = sb + SK + bf * 8192;
        const uint32_t vbase = sb + SV + bf * 32768;

        #pragma unroll
        for (int kc = 0; kc < 4; kc++) {
            float S[2][4];
            #pragma unroll
            for (int h = 0; h < 2; h++) {
                S[h][0] = S[h][1] = S[h][2] = S[h][3] = 0.f;
                int krow = (2 * kc + h) * 8 + l7;
                int swk = (krow & 7);
                uint32_t kh4[4], kl4[4];
                ldsm4(kh4, kbase + krow * 128 + ((lm4 ^ swk) << 4));
                ldsm4(kl4, kbase + krow * 128 + (((lm4 + 4) ^ swk) << 4));
                mma16816(S[h], qh[0], kh4[0], kh4[1]);
                mma16816(S[h], qh[1], kh4[2], kh4[3]);
                mma16816(S[h], qh[0], kl4[0], kl4[1]);
                mma16816(S[h], qh[1], kl4[2], kl4[3]);
                mma16816(S[h], ql[0], kh4[0], kh4[1]);
                mma16816(S[h], ql[1], kh4[2], kh4[3]);
            }

            uint32_t pah[4];
            #pragma unroll
            for (int h = 0; h < 2; h++) {
                float e0 = __expf(S[h][0] - mx0), e1 = __expf(S[h][1] - mx0);
                float e2 = __expf(S[h][2] - mx1), e3 = __expf(S[h][3] - mx1);
                rs0 += e0 + e1;
                rs1 += e2 + e3;
                pah[h * 2]     = packh(e0, e1);
                pah[h * 2 + 1] = packh(e2, e3);
            }

            int vrow = kc * 16 + l7 + lm8;
            uint32_t vroff = vbase + vrow * 512;
            int swv = (vrow & 7);
            #pragma unroll
            for (int vb = 0; vb < 16; vb++) {
                int ch = vb * 2 + lhi;
                uint32_t a = vroff + ((((ch & 24) | ((ch ^ swv) & 7))) << 4);
                uint32_t vh4[4];
                ldsm4t(vh4, a);
                mma16816(O[2 * vb],     pah, vh4[0], vh4[1]);
                mma16816(O[2 * vb + 1], pah, vh4[2], vh4[3]);
            }
        }
    }

    rs0 += __shfl_xor_sync(0xffffffffu, rs0, 1);
    rs0 += __shfl_xor_sync(0xffffffffu, rs0, 2);
    rs1 += __shfl_xor_sync(0xffffffffu, rs1, 1);
    rs1 += __shfl_xor_sync(0xffffffffu, rs1, 2);
    const float li0 = 1.0f / rs0, li1 = 1.0f / rs1;

    const int ng = i0 + w * 16 + rr;
    #pragma unroll
    for (int nb = 0; nb < 32; nb++) {
        int c = nb * 8 + qd * 2;
        size_t g = ((size_t)b * NC + c) * NN + ng;
        out[g]          = O[nb][0] * li0 + x[g];
        out[g + NN]     = O[nb][1] * li0 + x[g + NN];
        out[g + 8]      = O[nb][2] * li1 + x[g + 8];
        out[g + 8 + NN] = O[nb][3] * li1 + x[g + 8 + NN];
    }
}

// =====================================================================
// convert: x -> fp16 hi/lo planes; W -> fp16 hi/lo rows
// x has NB*NC*NN/4 = 1048576 float4 -> 2048 blocks x 512 float4 (kk<2).
// =====================================================================
__global__ __launch_bounds__(256) void convert_kernel(
    const float* __restrict__ x,
    const float* __restrict__ Wq, const float* __restrict__ Wk,
    const float* __restrict__ Wv)
{
    const int t = threadIdx.x;
    if (blockIdx.x < 2048) {
        const float4* xs = (const float4*)x;
        uint2* xh2 = (uint2*)g_xh;
        uint2* xl2 = (uint2*)g_xl;
        #pragma unroll
        for (int kk = 0; kk < 2; kk++) {
            size_t i = (size_t)blockIdx.x * 512 + kk * 256 + t;
            float4 v = xs[i];
            uint32_t h0 = packh(v.x, v.y), h1 = packh(v.z, v.w);
            float r0 = f16f((unsigned short)(h0 & 0xffffu));
            float r1 = f16f((unsigned short)(h0 >> 16));
            float r2 = f16f((unsigned short)(h1 & 0xffffu));
            float r3 = f16f((unsigned short)(h1 >> 16));
            xh2[i] = make_uint2(h0, h1);
            xl2[i] = make_uint2(packh(v.x - r0, v.y - r1), packh(v.z - r2, v.w - r3));
        }
    } else {
        // Wv: 16384 float4 ; Wq/Wk: 2048 float4 each
        uint2* vh2 = (uint2*)g_wvh;  uint2* vl2 = (uint2*)g_wvl;
        uint2* qh2 = (uint2*)g_wqkh; uint2* ql2 = (uint2*)g_wqkl;
        const float4* wv4 = (const float4*)Wv;
        for (int kk = 0; kk < 64; kk++) {
            int i = kk * 256 + t;
            float4 v = wv4[i];
            uint32_t h0 = packh(v.x, v.y), h1 = packh(v.z, v.w);
            float r0 = f16f((unsigned short)(h0 & 0xffffu));
            float r1 = f16f((unsigned short)(h0 >> 16));
            float r2 = f16f((unsigned short)(h1 & 0xffffu));
            float r3 = f16f((unsigned short)(h1 >> 16));
            vh2[i] = make_uint2(h0, h1);
            vl2[i] = make_uint2(packh(v.x - r0, v.y - r1), packh(v.z - r2, v.w - r3));
        }
        const float4* wq4 = (const float4*)Wq;
        const float4* wk4 = (const float4*)Wk;
        for (int kk = 0; kk < 8; kk++) {
            int i = kk * 256 + t;
            float4 v = wq4[i];
            uint32_t h0 = packh(v.x, v.y), h1 = packh(v.z, v.w);
            float r0 = f16f((unsigned short)(h0 & 0xffffu));
            float r1 = f16f((unsigned short)(h0 >> 16));
            float r2 = f16f((unsigned short)(h1 & 0xffffu));
            float r3 = f16f((unsigned short)(h1 >> 16));
            qh2[i] = make_uint2(h0, h1);
            ql2[i] = make_uint2(packh(v.x - r0, v.y - r1), packh(v.z - r2, v.w - r3));
            v = wk4[i];
            h0 = packh(v.x, v.y); h1 = packh(v.z, v.w);
            r0 = f16f((unsigned short)(h0 & 0xffffu));
            r1 = f16f((unsigned short)(h0 >> 16));
            r2 = f16f((unsigned short)(h1 & 0xffffu));
            r3 = f16f((unsigned short)(h1 >> 16));
            qh2[2048 + i] = make_uint2(h0, h1);
            ql2[2048 + i] = make_uint2(packh(v.x - r0, v.y - r1), packh(v.z - r2, v.w - r3));
        }
    }
}

// =====================================================================
// proj v2: pure fp16 pipelined GEMM, D[n][c] = x^T W^T (3-product hi/lo)
// =====================================================================
template<int NU, bool ISV>
__device__ __forceinline__ void proj_body(
    char* ps, uint32_t sb, int b, int n0, int c0,
    const float* __restrict__ bq, const float* __restrict__ bk,
    const float* __restrict__ bv)
{
    const int t = threadIdx.x, lane = t & 31, w = t >> 5;
    const int rr = lane >> 2, qd = lane & 3;
    const int l7 = lane & 7, lhi = lane >> 4, lm4 = lane >> 3, lq = (lane >> 3) & 1;
    const unsigned short* wh_g = ISV ? g_wvh : g_wqkh;
    const unsigned short* wl_g = ISV ? g_wvl : g_wqkl;

    // prefetch one k-tile (k0) into buffer bf
    auto prefetch = [&](int bf, int k0) {
        #pragma unroll
        for (int kk = 0; kk < 4; kk++) {
            int idx = t + kk * 256;
            int row = idx >> 5, ch = idx & 31;
            const unsigned short* src = (ch < 16 ? g_xh : g_xl)
                + ((size_t)(b * NC + k0 + row)) * NN + n0 + (ch & 15) * 8;
            cp16(sb + PJX + bf * 16384 + row * 512 + swz512(ch, row), src);
        }
        #pragma unroll
        for (int kk = 0; kk < (ISV ? 4 : 2); kk++) {
            int idx = t + kk * 256;
            int row = idx >> 3, ch = idx & 7;
            const unsigned short* src = (ch < 4 ? wh_g : wl_g)
                + (size_t)(c0 + row) * 256 + k0 + (ch & 3) * 8;
            cp16(sb + PJW + bf * 16384 + row * 128 + ((ch ^ (row & 7)) << 4), src);
        }
    };

    float O[NU][4];
    #pragma unroll
    for (int i = 0; i < NU; i++)
        #pragma unroll
        for (int j = 0; j < 4; j++) O[i][j] = 0.f;

    prefetch(0, 0);
    cp_commit();

    for (int it = 0; it < 8; it++) {
        const int buf = it & 1;
        cp_wait0();
        __syncthreads();
        if (it < 7) { prefetch(buf ^ 1, (it + 1) * 32); cp_commit(); }

        // A-frags: x^T via trans ldmatrix on [k][n] tile
        uint32_t ah[2][4], al[2][4];
        #pragma unroll
        for (int kc = 0; kc < 2; kc++) {
            int krow = kc * 16 + l7 + lhi * 8;
            int chA = 2 * w + lq;
            uint32_t base = sb + PJX + buf * 16384 + krow * 512;
            ldsm4t(ah[kc], base + swz512(chA, krow));
            ldsm4t(al[kc], base + swz512(chA + 16, krow));
        }
        // B-frags: W rows, 6 MMAs per 8-c block
        #pragma unroll
        for (int u = 0; u < NU; u++) {
            int crow = u * 8 + l7;
            uint32_t wb = sb + PJW + buf * 16384 + crow * 128;
            int sw = crow & 7;
            uint32_t whf[4], wlf[4];
            ldsm4(whf, wb + ((lm4 ^ sw) << 4));
            ldsm4(wlf, wb + (((lm4 + 4) ^ sw) << 4));
            mma16816(O[u], ah[0], whf[0], whf[1]);
            mma16816(O[u], ah[1], whf[2], whf[3]);
            mma16816(O[u], al[0], whf[0], whf[1]);
            mma16816(O[u], al[1], whf[2], whf[3]);
            mma16816(O[u], ah[0], wlf[0], wlf[1]);
            mma16816(O[u], ah[1], wlf[2], wlf[3]);
        }
    }

    const int n_lo = n0 + w * 16 + rr;
    if (ISV) {
        #pragma unroll
        for (int u = 0; u < NU; u++) {
            int c = c0 + u * 8 + qd * 2;
            float b0 = bv[c], b1 = bv[c + 1];
            uint32_t p0 = packh(O[u][0] + b0, O[u][1] + b1);
            uint32_t p1 = packh(O[u][2] + b0, O[u][3] + b1);
            *(uint32_t*)&g_v[((size_t)(b * NN + n_lo)) * 256 + c] = p0;
            *(uint32_t*)&g_v[((size_t)(b * NN + n_lo + 8)) * 256 + c] = p1;
        }
    } else {
        #pragma unroll
        for (int u = 0; u < NU; u++) {
            int c = u * 8 + qd * 2;
            bool isq = (c < 32);
            unsigned short* tgt = isq ? g_q : g_k;
            int cl = isq ? c : c - 32;
            const float* bb = isq ? bq : bk;
            float b0 = bb[cl], b1 = bb[cl + 1];
            #pragma unroll
            for (int hh = 0; hh < 2; hh++) {
                float v0 = O[u][2 * hh] + b0, v1 = O[u][2 * hh + 1] + b1;
                unsigned short h0 = f16h(v0), h1 = f16h(v1);
                uint32_t hp = ((uint32_t)h1 << 16) | h0;
                uint32_t lp = packh(v0 - f16f(h0), v1 - f16f(h1));
                size_t base = ((size_t)(b * NN + n_lo + hh * 8)) * 64;
                *(uint32_t*)&tgt[base + cl] = hp;
                *(uint32_t*)&tgt[base + 32 + cl] = lp;
            }
        }
    }
}

__global__ __launch_bounds__(256, 2) void proj_mma(
    const float* __restrict__ bq, const float* __restrict__ bk,
    const float* __restrict__ bv)
{
    extern __shared__ char ps[];
    const uint32_t sb = smem_u32(ps);
    const int b = blockIdx.z;
    if (blockIdx.x < 64) {
        proj_body<16, true>(ps, sb, b, (blockIdx.x >> 1) * 128,
                            (blockIdx.x & 1) * 128, bq, bk, bv);
    } else {
        proj_body<8, false>(ps, sb, b, ((int)blockIdx.x - 64) * 128, 0, bq, bk, bv);
    }
}

// =====================================================================
extern "C" void kernel_launch(void* const* d_in, const int* in_sizes, int n_in,
                              void* d_out, int out_size)
{
    const float* x  = (const float*)d_in[0];
    const float* Wq = (const float*)d_in[1];
    const float* bq = (const float*)d_in[2];
    const float* Wk = (const float*)d_in[3];
    const float* bk = (const float*)d_in[4];
    const float* Wv = (const float*)d_in[5];
    const float* bv = (const float*)d_in[6];
    float* out = (float*)d_out;

    cudaFuncSetAttribute(attn_kernel, cudaFuncAttributeMaxDynamicSharedMemorySize, SMEMB);
    cudaFuncSetAttribute(proj_mma, cudaFuncAttributeMaxDynamicSharedMemorySize, PJ_SMEM);

    convert_kernel<<<2049, 256>>>(x, Wq, Wk, Wv);
    proj_mma<<<dim3(96, 1, NB), 256, PJ_SMEM>>>(bq, bk, bv);
    attn_kernel<<<dim3(NN / TI, NB), 256, SMEMB>>>(x, out);
}

// round 13
// speedup vs baseline: 1.3895x; 1.0329x over previous
#include <cuda_runtime.h>
#include <cuda_fp16.h>
#include <cstdint>

#define NB 4
#define NC 256
#define NN 4096
#define TI 128
#define TJ 64
#define NSTEPS (NN / TJ)
#define TJ1 256
#define NSTEPS1 (NN / TJ1)

// ---------------- device scratch (allocation-free) ----------------
__device__ unsigned short g_q[(size_t)NB * NN * 64];     // [b][n][32hi|32lo] fp16
__device__ unsigned short g_k[(size_t)NB * NN * 64];
__device__ unsigned short g_v[(size_t)NB * NN * 256];    // [b][n][c] fp16
__device__ unsigned short g_xh[(size_t)NB * NC * NN];    // x hi plane [b][c][n]
__device__ unsigned short g_xl[(size_t)NB * NC * NN];    // x lo plane
__device__ unsigned short g_wvh[256 * 256];              // Wv hi [c][k]
__device__ unsigned short g_wvl[256 * 256];
__device__ unsigned short g_wqkh[64 * 256];              // Wq(0-31)|Wk(32-63) hi [c][k]
__device__ unsigned short g_wqkl[64 * 256];

// ---------------- attn SMEM layout (bytes) ----------------
#define SQ 0                       // 128 rows x 128B = 16384
#define SK 16384                   // + bf*8192 (64 rows x 128B)
#define SV 32768                   // + bf*32768 ; 64 j-rows x 512B
#define SMEMB (32768 + 2 * 32768)  // 98304

// ---------------- proj SMEM ----------------
#define PJX 0          // x tile: [2 buf][32 k][512B: 128n hi | 128n lo]
#define PJW 32768      // W tile: [2 buf][<=128 c][128B: 32k hi | 32k lo]
#define PJ_SMEM 65536

// ---------------- PTX helpers ----------------
__device__ __forceinline__ uint32_t smem_u32(const void* p) {
    uint32_t a;
    asm("{ .reg .u64 t; cvta.to.shared.u64 t, %1; cvt.u32.u64 %0, t; }" : "=r"(a) : "l"(p));
    return a;
}
__device__ __forceinline__ void cp16(uint32_t dst, const void* src) {
    asm volatile("cp.async.cg.shared.global [%0], [%1], 16;" :: "r"(dst), "l"(src));
}
__device__ __forceinline__ void cp_commit() { asm volatile("cp.async.commit_group;" ::: "memory"); }
__device__ __forceinline__ void cp_wait0()  { asm volatile("cp.async.wait_group 0;" ::: "memory"); }

__device__ __forceinline__ void ldsm4(uint32_t* r, uint32_t a) {
    asm volatile("ldmatrix.sync.aligned.m8n8.x4.shared.b16 {%0,%1,%2,%3}, [%4];"
        : "=r"(r[0]), "=r"(r[1]), "=r"(r[2]), "=r"(r[3]) : "r"(a));
}
__device__ __forceinline__ void ldsm4t(uint32_t* r, uint32_t a) {
    asm volatile("ldmatrix.sync.aligned.m8n8.x4.trans.shared.b16 {%0,%1,%2,%3}, [%4];"
        : "=r"(r[0]), "=r"(r[1]), "=r"(r[2]), "=r"(r[3]) : "r"(a));
}
__device__ __forceinline__ void mma16816(float* d, const uint32_t* a, uint32_t b0, uint32_t b1) {
    asm volatile("mma.sync.aligned.m16n8k16.row.col.f32.f16.f16.f32 "
        "{%0,%1,%2,%3}, {%4,%5,%6,%7}, {%8,%9}, {%0,%1,%2,%3};"
        : "+f"(d[0]), "+f"(d[1]), "+f"(d[2]), "+f"(d[3])
        : "r"(a[0]), "r"(a[1]), "r"(a[2]), "r"(a[3]), "r"(b0), "r"(b1));
}
// pack: first arg -> low half, second -> high half
__device__ __forceinline__ uint32_t packh(float lo, float hi) {
    uint32_t r;
    asm("cvt.rn.f16x2.f32 %0, %1, %2;" : "=r"(r) : "f"(hi), "f"(lo));
    return r;
}
__device__ __forceinline__ unsigned short f16h(float v) {
    __half h = __float2half_rn(v);
    return *reinterpret_cast<unsigned short*>(&h);
}
__device__ __forceinline__ float f16f(unsigned short u) {
    __half h = *reinterpret_cast<__half*>(&u);
    return __half2float(h);
}
__device__ __forceinline__ uint32_t swz512(int ch, int row) {
    return (uint32_t)(((ch & 24) | ((ch ^ (row & 7)) & 7)) << 4);
}
// convert one float4 to hi/lo fp16x2 pairs
__device__ __forceinline__ void cvt4(float4 v, uint2& hh, uint2& ll) {
    uint32_t h0 = packh(v.x, v.y), h1 = packh(v.z, v.w);
    float r0 = f16f((unsigned short)(h0 & 0xffffu));
    float r1 = f16f((unsigned short)(h0 >> 16));
    float r2 = f16f((unsigned short)(h1 & 0xffffu));
    float r3 = f16f((unsigned short)(h1 >> 16));
    hh = make_uint2(h0, h1);
    ll = make_uint2(packh(v.x - r0, v.y - r1), packh(v.z - r2, v.w - r3));
}

// ---------------- attn prefetchers (256 threads) ----------------
__device__ __forceinline__ void prefetch_k256(uint32_t sb, int bf, int b, int j0, int t) {
    #pragma unroll
    for (int kk = 0; kk < 4; kk++) {
        int idx = t + kk * 256;
        int row = idx >> 2, ch = idx & 3;
        cp16(sb + SV + bf * 16384 + row * 64 + ((ch ^ ((row >> 1) & 3)) << 4),
             g_k + ((size_t)(b * NN + j0 + row)) * 64 + ch * 8);
    }
}
__device__ __forceinline__ void prefetch_kv(uint32_t sb, int bf, int b, int j0, int t) {
    const unsigned short* ks = g_k + ((size_t)(b * NN + j0)) * 64;
    #pragma unroll
    for (int kk = 0; kk < 2; kk++) {
        int idx = t + kk * 256;
        int row = idx >> 3, ch = idx & 7;
        cp16(sb + SK + bf * 8192 + row * 128 + ((ch ^ (row & 7)) << 4),
             ks + (size_t)row * 64 + ch * 8);
    }
    const unsigned short* hs = g_v + ((size_t)(b * NN + j0)) * 256;
    #pragma unroll
    for (int kk = 0; kk < 8; kk++) {
        int idx = t + kk * 256;
        int row = idx >> 5, ch = idx & 31;
        uint32_t off = row * 512 + (((ch & 24) | ((ch ^ row) & 7)) << 4);
        cp16(sb + SV + bf * 32768 + off, hs + (size_t)row * 256 + ch * 8);
    }
}

// =====================================================================
// fp16 mma.sync flash attention (round-9 validated: TI=128, 8 warps)
// =====================================================================
__global__ __launch_bounds__(256, 1) void attn_kernel(
    const float* __restrict__ x, float* __restrict__ out)
{
    extern __shared__ char smem[];
    const uint32_t sb = smem_u32(smem);
    const int t = threadIdx.x, lane = t & 31, w = t >> 5;
    const int b = blockIdx.y, i0 = blockIdx.x * TI;
    const int rr = lane >> 2, qd = lane & 3;
    const int l7 = lane & 7, lm8 = ((lane >> 3) & 1) * 8, lhi = lane >> 4, lm4 = lane >> 3;

    {
        const unsigned short* qs = g_q + ((size_t)(b * NN + i0)) * 64;
        #pragma unroll
        for (int kk = 0; kk < 4; kk++) {
            int idx = t + kk * 256;
            int row = idx >> 3, ch = idx & 7;
            cp16(sb + SQ + row * 128 + ((ch ^ (row & 7)) << 4),
                 qs + (size_t)row * 64 + ch * 8);
        }
        prefetch_k256(sb, 0, b, 0, t);
        cp_commit();
    }
    cp_wait0();
    __syncthreads();

    uint32_t qh[2][4], ql[2][4];
    #pragma unroll
    for (int kc = 0; kc < 2; kc++) {
        int row = w * 16 + l7 + lm8;
        int chh = 2 * kc + lhi;
        ldsm4(qh[kc], sb + SQ + row * 128 + ((chh ^ (row & 7)) << 4));
        ldsm4(ql[kc], sb + SQ + row * 128 + (((chh + 4) ^ (row & 7)) << 4));
    }

    // ---- PHASE 1: row max ----
    float mx0 = -1e30f, mx1 = -1e30f;
    for (int it = 0; it < NSTEPS1; it++) {
        const int bf = it & 1;
        if (it > 0) { cp_wait0(); __syncthreads(); }
        if (it + 1 < NSTEPS1) { prefetch_k256(sb, bf ^ 1, b, (it + 1) * TJ1, t); cp_commit(); }
        const uint32_t kb = sb + SV + bf * 16384;
        #pragma unroll
        for (int hb = 0; hb < 32; hb++) {
            float S[4] = {0.f, 0.f, 0.f, 0.f};
            int krow = hb * 8 + l7;
            uint32_t a = kb + krow * 64 + ((lm4 ^ ((krow >> 1) & 3)) << 4);
            uint32_t kh4[4];
            ldsm4(kh4, a);
            mma16816(S, qh[0], kh4[0], kh4[1]);
            mma16816(S, qh[1], kh4[2], kh4[3]);
            mx0 = fmaxf(mx0, fmaxf(S[0], S[1]));
            mx1 = fmaxf(mx1, fmaxf(S[2], S[3]));
        }
    }
    mx0 = fmaxf(mx0, __shfl_xor_sync(0xffffffffu, mx0, 1));
    mx0 = fmaxf(mx0, __shfl_xor_sync(0xffffffffu, mx0, 2));
    mx1 = fmaxf(mx1, __shfl_xor_sync(0xffffffffu, mx1, 1));
    mx1 = fmaxf(mx1, __shfl_xor_sync(0xffffffffu, mx1, 2));

    // ---- PHASE 2 ----
    float O[32][4];
    #pragma unroll
    for (int i = 0; i < 32; i++)
        #pragma unroll
        for (int j = 0; j < 4; j++) O[i][j] = 0.f;
    float rs0 = 0.f, rs1 = 0.f;

    __syncthreads();
    prefetch_kv(sb, 0, b, 0, t);
    cp_commit();
    cp_wait0();
    __syncthreads();

    for (int st = 0; st < NSTEPS; st++) {
        const int bf = st & 1;
        if (st > 0) { cp_wait0(); __syncthreads(); }
        if (st + 1 < NSTEPS) { prefetch_kv(sb, bf ^ 1, b, (st + 1) * TJ, t); cp_commit(); }

        const uint32_t kbase = sb + SK + bf * 8192;
        const uint32_t vbase = sb + SV + bf * 32768;

        #pragma unroll
        for (int kc = 0; kc < 4; kc++) {
            float S[2][4];
            #pragma unroll
            for (int h = 0; h < 2; h++) {
                S[h][0] = S[h][1] = S[h][2] = S[h][3] = 0.f;
                int krow = (2 * kc + h) * 8 + l7;
                int swk = (krow & 7);
                uint32_t kh4[4], kl4[4];
                ldsm4(kh4, kbase + krow * 128 + ((lm4 ^ swk) << 4));
                ldsm4(kl4, kbase + krow * 128 + (((lm4 + 4) ^ swk) << 4));
                mma16816(S[h], qh[0], kh4[0], kh4[1]);
                mma16816(S[h], qh[1], kh4[2], kh4[3]);
                mma16816(S[h], qh[0], kl4[0], kl4[1]);
                mma16816(S[h], qh[1], kl4[2], kl4[3]);
                mma16816(S[h], ql[0], kh4[0], kh4[1]);
                mma16816(S[h], ql[1], kh4[2], kh4[3]);
            }

            uint32_t pah[4];
            #pragma unroll
            for (int h = 0; h < 2; h++) {
                float e0 = __expf(S[h][0] - mx0), e1 = __expf(S[h][1] - mx0);
                float e2 = __expf(S[h][2] - mx1), e3 = __expf(S[h][3] - mx1);
                rs0 += e0 + e1;
                rs1 += e2 + e3;
                pah[h * 2]     = packh(e0, e1);
                pah[h * 2 + 1] = packh(e2, e3);
            }

            int vrow = kc * 16 + l7 + lm8;
            uint32_t vroff = vbase + vrow * 512;
            int swv = (vrow & 7);
            #pragma unroll
            for (int vb = 0; vb < 16; vb++) {
                int ch = vb * 2 + lhi;
                uint32_t a = vroff + ((((ch & 24) | ((ch ^ swv) & 7))) << 4);
                uint32_t vh4[4];
                ldsm4t(vh4, a);
                mma16816(O[2 * vb],     pah, vh4[0], vh4[1]);
                mma16816(O[2 * vb + 1], pah, vh4[2], vh4[3]);
            }
        }
    }

    rs0 += __shfl_xor_sync(0xffffffffu, rs0, 1);
    rs0 += __shfl_xor_sync(0xffffffffu, rs0, 2);
    rs1 += __shfl_xor_sync(0xffffffffu, rs1, 1);
    rs1 += __shfl_xor_sync(0xffffffffu, rs1, 2);
    const float li0 = 1.0f / rs0, li1 = 1.0f / rs1;

    const int ng = i0 + w * 16 + rr;
    #pragma unroll
    for (int nb = 0; nb < 32; nb++) {
        int c = nb * 8 + qd * 2;
        size_t g = ((size_t)b * NC + c) * NN + ng;
        out[g]          = O[nb][0] * li0 + x[g];
        out[g + NN]     = O[nb][1] * li0 + x[g + NN];
        out[g + 8]      = O[nb][2] * li1 + x[g + 8];
        out[g + 8 + NN] = O[nb][3] * li1 + x[g + 8 + NN];
    }
}

// =====================================================================
// convert: x -> fp16 hi/lo planes (blocks 0-1023, 4 f4/thread);
// Wv -> blocks 1024-1039; Wq -> 1040-1041; Wk -> 1042-1043.
// =====================================================================
__global__ __launch_bounds__(256) void convert_kernel(
    const float* __restrict__ x,
    const float* __restrict__ Wq, const float* __restrict__ Wk,
    const float* __restrict__ Wv)
{
    const int t = threadIdx.x;
    const int bx = blockIdx.x;
    if (bx < 1024) {
        const float4* xs = (const float4*)x;
        uint2* xh2 = (uint2*)g_xh;
        uint2* xl2 = (uint2*)g_xl;
        float4 v[4];
        size_t base = (size_t)bx * 1024 + t;
        #pragma unroll
        for (int kk = 0; kk < 4; kk++) v[kk] = xs[base + kk * 256];
        #pragma unroll
        for (int kk = 0; kk < 4; kk++) {
            uint2 hh, ll;
            cvt4(v[kk], hh, ll);
            xh2[base + kk * 256] = hh;
            xl2[base + kk * 256] = ll;
        }
    } else if (bx < 1040) {
        const float4* wv4 = (const float4*)Wv;
        uint2* vh2 = (uint2*)g_wvh;
        uint2* vl2 = (uint2*)g_wvl;
        float4 v[4];
        int base = (bx - 1024) * 1024 + t;
        #pragma unroll
        for (int kk = 0; kk < 4; kk++) v[kk] = wv4[base + kk * 256];
        #pragma unroll
        for (int kk = 0; kk < 4; kk++) {
            uint2 hh, ll;
            cvt4(v[kk], hh, ll);
            vh2[base + kk * 256] = hh;
            vl2[base + kk * 256] = ll;
        }
    } else {
        const bool isQ = bx < 1042;
        const float4* w4 = (const float4*)(isQ ? Wq : Wk);
        int base = ((bx - (isQ ? 1040 : 1042)) & 1) * 1024 + t;
        int off = isQ ? 0 : 2048;
        uint2* h2 = (uint2*)g_wqkh;
        uint2* l2 = (uint2*)g_wqkl;
        float4 v[4];
        #pragma unroll
        for (int kk = 0; kk < 4; kk++) v[kk] = w4[base + kk * 256];
        #pragma unroll
        for (int kk = 0; kk < 4; kk++) {
            uint2 hh, ll;
            cvt4(v[kk], hh, ll);
            h2[off + base + kk * 256] = hh;
            l2[off + base + kk * 256] = ll;
        }
    }
}

// =====================================================================
// proj v2: pure fp16 pipelined GEMM, D[n][c] = x^T W^T (3-product hi/lo)
// =====================================================================
template<int NU, bool ISV>
__device__ __forceinline__ void proj_body(
    char* ps, uint32_t sb, int b, int n0, int c0,
    const float* __restrict__ bq, const float* __restrict__ bk,
    const float* __restrict__ bv)
{
    const int t = threadIdx.x, lane = t & 31, w = t >> 5;
    const int rr = lane >> 2, qd = lane & 3;
    const int l7 = lane & 7, lhi = lane >> 4, lm4 = lane >> 3, lq = (lane >> 3) & 1;
    const unsigned short* wh_g = ISV ? g_wvh : g_wqkh;
    const unsigned short* wl_g = ISV ? g_wvl : g_wqkl;

    auto prefetch = [&](int bf, int k0) {
        #pragma unroll
        for (int kk = 0; kk < 4; kk++) {
            int idx = t + kk * 256;
            int row = idx >> 5, ch = idx & 31;
            const unsigned short* src = (ch < 16 ? g_xh : g_xl)
                + ((size_t)(b * NC + k0 + row)) * NN + n0 + (ch & 15) * 8;
            cp16(sb + PJX + bf * 16384 + row * 512 + swz512(ch, row), src);
        }
        #pragma unroll
        for (int kk = 0; kk < (ISV ? 4 : 2); kk++) {
            int idx = t + kk * 256;
            int row = idx >> 3, ch = idx & 7;
            const unsigned short* src = (ch < 4 ? wh_g : wl_g)
                + (size_t)(c0 + row) * 256 + k0 + (ch & 3) * 8;
            cp16(sb + PJW + bf * 16384 + row * 128 + ((ch ^ (row & 7)) << 4), src);
        }
    };

    float O[NU][4];
    #pragma unroll
    for (int i = 0; i < NU; i++)
        #pragma unroll
        for (int j = 0; j < 4; j++) O[i][j] = 0.f;

    prefetch(0, 0);
    cp_commit();

    for (int it = 0; it < 8; it++) {
        const int buf = it & 1;
        cp_wait0();
        __syncthreads();
        if (it < 7) { prefetch(buf ^ 1, (it + 1) * 32); cp_commit(); }

        uint32_t ah[2][4], al[2][4];
        #pragma unroll
        for (int kc = 0; kc < 2; kc++) {
            int krow = kc * 16 + l7 + lhi * 8;
            int chA = 2 * w + lq;
            uint32_t base = sb + PJX + buf * 16384 + krow * 512;
            ldsm4t(ah[kc], base + swz512(chA, krow));
            ldsm4t(al[kc], base + swz512(chA + 16, krow));
        }
        #pragma unroll
        for (int u = 0; u < NU; u++) {
            int crow = u * 8 + l7;
            uint32_t wb = sb + PJW + buf * 16384 + crow * 128;
            int sw = crow & 7;
            uint32_t whf[4], wlf[4];
            ldsm4(whf, wb + ((lm4 ^ sw) << 4));
            ldsm4(wlf, wb + (((lm4 + 4) ^ sw) << 4));
            mma16816(O[u], ah[0], whf[0], whf[1]);
            mma16816(O[u], ah[1], whf[2], whf[3]);
            mma16816(O[u], al[0], whf[0], whf[1]);
            mma16816(O[u], al[1], whf[2], whf[3]);
            mma16816(O[u], ah[0], wlf[0], wlf[1]);
            mma16816(O[u], ah[1], wlf[2], wlf[3]);
        }
    }

    const int n_lo = n0 + w * 16 + rr;
    if (ISV) {
        #pragma unroll
        for (int u = 0; u < NU; u++) {
            int c = c0 + u * 8 + qd * 2;
            float b0 = bv[c], b1 = bv[c + 1];
            uint32_t p0 = packh(O[u][0] + b0, O[u][1] + b1);
            uint32_t p1 = packh(O[u][2] + b0, O[u][3] + b1);
            *(uint32_t*)&g_v[((size_t)(b * NN + n_lo)) * 256 + c] = p0;
            *(uint32_t*)&g_v[((size_t)(b * NN + n_lo + 8)) * 256 + c] = p1;
        }
    } else {
        #pragma unroll
        for (int u = 0; u < NU; u++) {
            int c = u * 8 + qd * 2;
            bool isq = (c < 32);
            unsigned short* tgt = isq ? g_q : g_k;
            int cl = isq ? c : c - 32;
            const float* bb = isq ? bq : bk;
            float b0 = bb[cl], b1 = bb[cl + 1];
            #pragma unroll
            for (int hh = 0; hh < 2; hh++) {
                float v0 = O[u][2 * hh] + b0, v1 = O[u][2 * hh + 1] + b1;
                unsigned short h0 = f16h(v0), h1 = f16h(v1);
                uint32_t hp = ((uint32_t)h1 << 16) | h0;
                uint32_t lp = packh(v0 - f16f(h0), v1 - f16f(h1));
                size_t base = ((size_t)(b * NN + n_lo + hh * 8)) * 64;
                *(uint32_t*)&tgt[base + cl] = hp;
                *(uint32_t*)&tgt[base + 32 + cl] = lp;
            }
        }
    }
}

__global__ __launch_bounds__(256, 2) void proj_mma(
    const float* __restrict__ bq, const float* __restrict__ bk,
    const float* __restrict__ bv)
{
    extern __shared__ char ps[];
    const uint32_t sb = smem_u32(ps);
    const int b = blockIdx.z;
    if (blockIdx.x < 64) {
        proj_body<16, true>(ps, sb, b, (blockIdx.x >> 1) * 128,
                            (blockIdx.x & 1) * 128, bq, bk, bv);
    } else {
        proj_body<8, false>(ps, sb, b, ((int)blockIdx.x - 64) * 128, 0, bq, bk, bv);
    }
}

// =====================================================================
extern "C" void kernel_launch(void* const* d_in, const int* in_sizes, int n_in,
                              void* d_out, int out_size)
{
    const float* x  = (const float*)d_in[0];
    const float* Wq = (const float*)d_in[1];
    const float* bq = (const float*)d_in[2];
    const float* Wk = (const float*)d_in[3];
    const float* bk = (const float*)d_in[4];
    const float* Wv = (const float*)d_in[5];
    const float* bv = (const float*)d_in[6];
    float* out = (float*)d_out;

    cudaFuncSetAttribute(attn_kernel, cudaFuncAttributeMaxDynamicSharedMemorySize, SMEMB);
    cudaFuncSetAttribute(proj_mma, cudaFuncAttributeMaxDynamicSharedMemorySize, PJ_SMEM);

    convert_kernel<<<1044, 256>>>(x, Wq, Wk, Wv);
    proj_mma<<<dim3(96, 1, NB), 256, PJ_SMEM>>>(bq, bk, bv);
    attn_kernel<<<dim3(NN / TI, NB), 256, SMEMB>>>(x, out);
}